// round 11
// baseline (speedup 1.0000x reference)
#include <cuda_runtime.h>

// MLP: 4 -> 8 -> 16 -> 32 -> 16 -> 8 -> 4, ReLU after every layer. N=4M, fp32.
// Round 11: round-10 base + PORT SPLIT: W3 (the largest layer, 512 pairs) is
// staged in shared memory and read via LDS.128; everything else stays in
// constant (LDC.128). Rationale: LDC has an 8-cyc/SMSP structural floor
// (half-rate constant port) -> at 672 LDC.128/warp the constant port needed
// exactly as many cycles as the FFMA2 pipe (284K/SMSP each). Splitting the
// traffic leaves FFMA2 as the sole binder.

#define NROWS 4000000

typedef unsigned long long u64;

// ---- layout of the repacked weight buffer (units: 8-byte dup'd pairs) ----
static constexpr int OFF_W1 = 0,    OFF_B1 = 32;     // 4x8   (transposed [j][k])
static constexpr int OFF_W2 = 40,   OFF_B2 = 168;    // 8x16  (transposed)
static constexpr int OFF_W3 = 184,  OFF_B3 = 696;    // 16x32 (transposed)
static constexpr int OFF_W4 = 728,  OFF_B4 = 1240;   // 32x16 (k-major [k][j])
static constexpr int OFF_W5 = 1256, OFF_B5 = 1384;   // 16x8  (transposed)
static constexpr int OFF_W6 = 1392, OFF_B6 = 1424;   // 8x4   (transposed)
static constexpr int TOTAL_PAIRS = 1428;              // 11,424 bytes
static constexpr int W3_PAIRS = 512;                  // 16x32 dup'd pairs

__device__ u64 g_wbuf[TOTAL_PAIRS];        // staging (written by repack kernel)
__constant__ __align__(16) u64 cw[TOTAL_PAIRS];   // hot copy (memcpy node)

// ---- packed f32x2 helpers ------------------------------------------------

__device__ __forceinline__ u64 fma2(u64 a, u64 b, u64 c) {
    u64 d;
    asm("fma.rn.f32x2 %0, %1, %2, %3;" : "=l"(d) : "l"(a), "l"(b), "l"(c));
    return d;
}

__device__ __forceinline__ u64 pack2(float lo, float hi) {
    u64 d;
    asm("mov.b64 %0, {%1, %2};" : "=l"(d) : "f"(lo), "f"(hi));
    return d;
}

__device__ __forceinline__ void unpack2(u64 v, float& lo, float& hi) {
    asm("mov.b64 {%0, %1}, %2;" : "=f"(lo), "=f"(hi) : "l"(v));
}

// ReLU on a packed pair: two FMNMX on the register halves (alu pipe).
__device__ __forceinline__ u64 relu2(u64 v) {
    float lo, hi;
    unpack2(v, lo, hi);
    lo = fmaxf(lo, 0.0f);
    hi = fmaxf(hi, 0.0f);
    return pack2(lo, hi);
}

__device__ __forceinline__ u64 dup2(float w) { return pack2(w, w); }

// 128-bit constant load (two adjacent dup'd weight pairs).
__device__ __forceinline__ ulonglong2 cw2(int idx) {
    return *reinterpret_cast<const ulonglong2*>(&cw[idx]);
}

// ---- repack kernel: duplicate + transpose weights into g_wbuf -------------

__device__ __forceinline__ void fill_t(
    const float* __restrict__ W, const float* __restrict__ B,
    int offW, int offB, int K, int OUT)
{
    for (int t = threadIdx.x; t < K * OUT; t += blockDim.x) {
        int j = t / K;
        int k = t - j * K;
        g_wbuf[offW + t] = dup2(W[k * OUT + j]);   // transposed [j][k]
    }
    for (int t = threadIdx.x; t < OUT; t += blockDim.x)
        g_wbuf[offB + t] = dup2(B[t]);
}

__device__ __forceinline__ void fill_k(
    const float* __restrict__ W, const float* __restrict__ B,
    int offW, int offB, int K, int OUT)
{
    for (int t = threadIdx.x; t < K * OUT; t += blockDim.x)
        g_wbuf[offW + t] = dup2(W[t]);             // k-major [k][j] as stored
    for (int t = threadIdx.x; t < OUT; t += blockDim.x)
        g_wbuf[offB + t] = dup2(B[t]);
}

__global__ void repack_kernel(
    const float* __restrict__ W1, const float* __restrict__ b1,
    const float* __restrict__ W2, const float* __restrict__ b2,
    const float* __restrict__ W3, const float* __restrict__ b3,
    const float* __restrict__ W4, const float* __restrict__ b4,
    const float* __restrict__ W5, const float* __restrict__ b5,
    const float* __restrict__ W6, const float* __restrict__ b6)
{
    fill_t(W1, b1, OFF_W1, OFF_B1, 4, 8);
    fill_t(W2, b2, OFF_W2, OFF_B2, 8, 16);
    fill_t(W3, b3, OFF_W3, OFF_B3, 16, 32);
    fill_k(W4, b4, OFF_W4, OFF_B4, 32, 16);
    fill_t(W5, b5, OFF_W5, OFF_B5, 16, 8);
    fill_t(W6, b6, OFF_W6, OFF_B6, 8, 4);
}

// ---- main MLP kernel -------------------------------------------------------

// Layer on TWO row-pairs, output-j unrolled x2 -> 4 independent FMA chains.
// Weights from constant memory.
template <int K, int OUT, int OFFW, int OFFB>
__device__ __forceinline__ void layer2x(
    const u64* hinA, const u64* hinB, u64* houtA, u64* houtB)
{
#pragma unroll
    for (int j = 0; j < OUT; j += 2) {
        u64 accA0 = cw[OFFB + j];
        u64 accB0 = accA0;
        u64 accA1 = cw[OFFB + j + 1];
        u64 accB1 = accA1;
#pragma unroll
        for (int k = 0; k < K; k += 2) {
            ulonglong2 w0 = cw2(OFFW + j * K + k);
            ulonglong2 w1 = cw2(OFFW + (j + 1) * K + k);
            accA0 = fma2(hinA[k],     w0.x, accA0);
            accB0 = fma2(hinB[k],     w0.x, accB0);
            accA1 = fma2(hinA[k],     w1.x, accA1);
            accB1 = fma2(hinB[k],     w1.x, accB1);
            accA0 = fma2(hinA[k + 1], w0.y, accA0);
            accB0 = fma2(hinB[k + 1], w0.y, accB0);
            accA1 = fma2(hinA[k + 1], w1.y, accA1);
            accB1 = fma2(hinB[k + 1], w1.y, accB1);
        }
        houtA[j]     = relu2(accA0);
        houtB[j]     = relu2(accB0);
        houtA[j + 1] = relu2(accA1);
        houtB[j + 1] = relu2(accB1);
    }
}

__global__ __launch_bounds__(128, 3)
void mlp_const_kernel(
    const float4* __restrict__ x,      // [N] rows of 4 floats
    float4* __restrict__ out)
{
    // W3 staged in shared memory (read via the LDS port instead of LDC).
    __shared__ __align__(16) u64 sw3[W3_PAIRS];
    for (int t = threadIdx.x; t < W3_PAIRS; t += 128)
        sw3[t] = cw[OFF_W3 + t];
    __syncthreads();

    const long long tid = (long long)blockIdx.x * blockDim.x + threadIdx.x;
    const long long row = tid * 4;
    if (row >= NROWS) return;            // N % 4 == 0 -> all 4 rows valid

    // Pair A = rows (row, row+1), pair B = rows (row+2, row+3)
    float4 x0 = x[row];
    float4 x1 = x[row + 1];
    float4 x2 = x[row + 2];
    float4 x3 = x[row + 3];

    u64 h0A[4], h0B[4];
    h0A[0] = pack2(x0.x, x1.x);  h0B[0] = pack2(x2.x, x3.x);
    h0A[1] = pack2(x0.y, x1.y);  h0B[1] = pack2(x2.y, x3.y);
    h0A[2] = pack2(x0.z, x1.z);  h0B[2] = pack2(x2.z, x3.z);
    h0A[3] = pack2(x0.w, x1.w);  h0B[3] = pack2(x2.w, x3.w);

    u64 h1A[8], h1B[8];
    layer2x<4, 8, OFF_W1, OFF_B1>(h0A, h0B, h1A, h1B);

    u64 h2A[16], h2B[16];
    layer2x<8, 16, OFF_W2, OFF_B2>(h1A, h1B, h2A, h2B);

    // ---- fused layer3 (16->32, W3 from SMEM) + layer4 (32->16, W4 const) ---
    u64 acc4A[16], acc4B[16];
    {
#pragma unroll
        for (int j = 0; j < 16; j++) {
            acc4A[j] = cw[OFF_B4 + j];
            acc4B[j] = acc4A[j];
        }
#pragma unroll
        for (int j3 = 0; j3 < 32; j3 += 2) {
            u64 aA0 = cw[OFF_B3 + j3];
            u64 aB0 = aA0;
            u64 aA1 = cw[OFF_B3 + j3 + 1];
            u64 aB1 = aA1;
#pragma unroll
            for (int k = 0; k < 16; k += 2) {
                ulonglong2 w0 = *reinterpret_cast<const ulonglong2*>(&sw3[j3 * 16 + k]);
                ulonglong2 w1 = *reinterpret_cast<const ulonglong2*>(&sw3[(j3 + 1) * 16 + k]);
                aA0 = fma2(h2A[k],     w0.x, aA0);
                aB0 = fma2(h2B[k],     w0.x, aB0);
                aA1 = fma2(h2A[k],     w1.x, aA1);
                aB1 = fma2(h2B[k],     w1.x, aB1);
                aA0 = fma2(h2A[k + 1], w0.y, aA0);
                aB0 = fma2(h2B[k + 1], w0.y, aB0);
                aA1 = fma2(h2A[k + 1], w1.y, aA1);
                aB1 = fma2(h2B[k + 1], w1.y, aB1);
            }
            aA0 = relu2(aA0);
            aB0 = relu2(aB0);
            aA1 = relu2(aA1);
            aB1 = relu2(aB1);
            // accumulate both h3 elements into all 16 layer-4 outputs
#pragma unroll
            for (int j4 = 0; j4 < 16; j4 += 2) {
                ulonglong2 w0 = cw2(OFF_W4 + j3 * 16 + j4);       // k-major row j3
                ulonglong2 w1 = cw2(OFF_W4 + (j3 + 1) * 16 + j4); // row j3+1
                acc4A[j4]     = fma2(aA0, w0.x, acc4A[j4]);
                acc4B[j4]     = fma2(aB0, w0.x, acc4B[j4]);
                acc4A[j4 + 1] = fma2(aA0, w0.y, acc4A[j4 + 1]);
                acc4B[j4 + 1] = fma2(aB0, w0.y, acc4B[j4 + 1]);
                acc4A[j4]     = fma2(aA1, w1.x, acc4A[j4]);
                acc4B[j4]     = fma2(aB1, w1.x, acc4B[j4]);
                acc4A[j4 + 1] = fma2(aA1, w1.y, acc4A[j4 + 1]);
                acc4B[j4 + 1] = fma2(aB1, w1.y, acc4B[j4 + 1]);
            }
        }
#pragma unroll
        for (int j = 0; j < 16; j++) {
            acc4A[j] = relu2(acc4A[j]);
            acc4B[j] = relu2(acc4B[j]);
        }
    }

    u64 h5A[8], h5B[8];
    layer2x<16, 8, OFF_W5, OFF_B5>(acc4A, acc4B, h5A, h5B);

    u64 h6A[4], h6B[4];
    layer2x<8, 4, OFF_W6, OFF_B6>(h5A, h5B, h6A, h6B);

    float4 o0, o1, o2, o3;
    unpack2(h6A[0], o0.x, o1.x);  unpack2(h6B[0], o2.x, o3.x);
    unpack2(h6A[1], o0.y, o1.y);  unpack2(h6B[1], o2.y, o3.y);
    unpack2(h6A[2], o0.z, o1.z);  unpack2(h6B[2], o2.z, o3.z);
    unpack2(h6A[3], o0.w, o1.w);  unpack2(h6B[3], o2.w, o3.w);
    out[row]     = o0;
    out[row + 1] = o1;
    out[row + 2] = o2;
    out[row + 3] = o3;
}

extern "C" void kernel_launch(void* const* d_in, const int* in_sizes, int n_in,
                              void* d_out, int out_size)
{
    const float* x  = (const float*)d_in[0];
    const float* W1 = (const float*)d_in[1];
    const float* b1 = (const float*)d_in[2];
    const float* W2 = (const float*)d_in[3];
    const float* b2 = (const float*)d_in[4];
    const float* W3 = (const float*)d_in[5];
    const float* b3 = (const float*)d_in[6];
    const float* W4 = (const float*)d_in[7];
    const float* b4 = (const float*)d_in[8];
    const float* W5 = (const float*)d_in[9];
    const float* b5 = (const float*)d_in[10];
    const float* W6 = (const float*)d_in[11];
    const float* b6 = (const float*)d_in[12];

    // 1) repack weights into g_wbuf (dup'd pairs, transposed)
    repack_kernel<<<1, 256>>>(W1, b1, W2, b2, W3, b3, W4, b4, W5, b5, W6, b6);

    // 2) copy staging buffer into constant memory (D2D memcpy node)
    void* wbuf_addr = nullptr;
    cudaGetSymbolAddress(&wbuf_addr, g_wbuf);
    cudaMemcpyToSymbolAsync(cw, wbuf_addr, TOTAL_PAIRS * sizeof(u64), 0,
                            cudaMemcpyDeviceToDevice, 0);

    // 3) main kernel
    const int threads = 128;
    const long long nthreads = (NROWS + 3) / 4;
    const int blocks = (int)((nthreads + threads - 1) / threads);

    mlp_const_kernel<<<blocks, threads>>>((const float4*)x, (float4*)d_out);
}

// round 12
// speedup vs baseline: 1.1962x; 1.1962x over previous
#include <cuda_runtime.h>

// MLP: 4 -> 8 -> 16 -> 32 -> 16 -> 8 -> 4, ReLU after every layer. N=4M, fp32.
// Round 12: 2 rows/thread (ONE f32x2 pair) + launch_bounds(128,5).
// Halving per-thread state (~146 -> ~95 regs) buys 5 warps/SMSP (vs 3),
// hiding the FFMA2 lat-4 / LDCU-return bubbles that held round 10 at fma=69%.
// Constant/UR weight path kept (round 11 proved the LDC port is not binding).

#define NROWS 4000000

typedef unsigned long long u64;

// ---- layout of the repacked weight buffer (units: 8-byte dup'd pairs) ----
static constexpr int OFF_W1 = 0,    OFF_B1 = 32;     // 4x8   (transposed [j][k])
static constexpr int OFF_W2 = 40,   OFF_B2 = 168;    // 8x16  (transposed)
static constexpr int OFF_W3 = 184,  OFF_B3 = 696;    // 16x32 (transposed)
static constexpr int OFF_W4 = 728,  OFF_B4 = 1240;   // 32x16 (k-major [k][j])
static constexpr int OFF_W5 = 1256, OFF_B5 = 1384;   // 16x8  (transposed)
static constexpr int OFF_W6 = 1392, OFF_B6 = 1424;   // 8x4   (transposed)
static constexpr int TOTAL_PAIRS = 1428;              // 11,424 bytes

__device__ u64 g_wbuf[TOTAL_PAIRS];        // staging (written by repack kernel)
__constant__ __align__(16) u64 cw[TOTAL_PAIRS];   // hot copy (memcpy node)

// ---- packed f32x2 helpers ------------------------------------------------

__device__ __forceinline__ u64 fma2(u64 a, u64 b, u64 c) {
    u64 d;
    asm("fma.rn.f32x2 %0, %1, %2, %3;" : "=l"(d) : "l"(a), "l"(b), "l"(c));
    return d;
}

__device__ __forceinline__ u64 pack2(float lo, float hi) {
    u64 d;
    asm("mov.b64 %0, {%1, %2};" : "=l"(d) : "f"(lo), "f"(hi));
    return d;
}

__device__ __forceinline__ void unpack2(u64 v, float& lo, float& hi) {
    asm("mov.b64 {%0, %1}, %2;" : "=f"(lo), "=f"(hi) : "l"(v));
}

// ReLU on a packed pair: two FMNMX on the register halves (alu pipe).
__device__ __forceinline__ u64 relu2(u64 v) {
    float lo, hi;
    unpack2(v, lo, hi);
    lo = fmaxf(lo, 0.0f);
    hi = fmaxf(hi, 0.0f);
    return pack2(lo, hi);
}

__device__ __forceinline__ u64 dup2(float w) { return pack2(w, w); }

// 128-bit constant load (two adjacent dup'd weight pairs).
__device__ __forceinline__ ulonglong2 cw2(int idx) {
    return *reinterpret_cast<const ulonglong2*>(&cw[idx]);
}

// ---- repack kernel: duplicate + transpose weights into g_wbuf -------------

__device__ __forceinline__ void fill_t(
    const float* __restrict__ W, const float* __restrict__ B,
    int offW, int offB, int K, int OUT)
{
    for (int t = threadIdx.x; t < K * OUT; t += blockDim.x) {
        int j = t / K;
        int k = t - j * K;
        g_wbuf[offW + t] = dup2(W[k * OUT + j]);   // transposed [j][k]
    }
    for (int t = threadIdx.x; t < OUT; t += blockDim.x)
        g_wbuf[offB + t] = dup2(B[t]);
}

__device__ __forceinline__ void fill_k(
    const float* __restrict__ W, const float* __restrict__ B,
    int offW, int offB, int K, int OUT)
{
    for (int t = threadIdx.x; t < K * OUT; t += blockDim.x)
        g_wbuf[offW + t] = dup2(W[t]);             // k-major [k][j] as stored
    for (int t = threadIdx.x; t < OUT; t += blockDim.x)
        g_wbuf[offB + t] = dup2(B[t]);
}

__global__ void repack_kernel(
    const float* __restrict__ W1, const float* __restrict__ b1,
    const float* __restrict__ W2, const float* __restrict__ b2,
    const float* __restrict__ W3, const float* __restrict__ b3,
    const float* __restrict__ W4, const float* __restrict__ b4,
    const float* __restrict__ W5, const float* __restrict__ b5,
    const float* __restrict__ W6, const float* __restrict__ b6)
{
    fill_t(W1, b1, OFF_W1, OFF_B1, 4, 8);
    fill_t(W2, b2, OFF_W2, OFF_B2, 8, 16);
    fill_t(W3, b3, OFF_W3, OFF_B3, 16, 32);
    fill_k(W4, b4, OFF_W4, OFF_B4, 32, 16);
    fill_t(W5, b5, OFF_W5, OFF_B5, 16, 8);
    fill_t(W6, b6, OFF_W6, OFF_B6, 8, 4);
}

// ---- main MLP kernel -------------------------------------------------------

// One layer on ONE row-pair, output-j unrolled x2 -> 2 independent chains.
template <int K, int OUT, int OFFW, int OFFB>
__device__ __forceinline__ void layer1x(const u64* hin, u64* hout)
{
#pragma unroll
    for (int j = 0; j < OUT; j += 2) {
        u64 a0 = cw[OFFB + j];
        u64 a1 = cw[OFFB + j + 1];
#pragma unroll
        for (int k = 0; k < K; k += 2) {
            ulonglong2 w0 = cw2(OFFW + j * K + k);
            ulonglong2 w1 = cw2(OFFW + (j + 1) * K + k);
            a0 = fma2(hin[k],     w0.x, a0);
            a1 = fma2(hin[k],     w1.x, a1);
            a0 = fma2(hin[k + 1], w0.y, a0);
            a1 = fma2(hin[k + 1], w1.y, a1);
        }
        hout[j]     = relu2(a0);
        hout[j + 1] = relu2(a1);
    }
}

// Fused layer3 (16->32) + layer4 (32->16), h3 streamed, one pair.
__device__ __forceinline__ void fused34(const u64* h2, u64* acc4)
{
#pragma unroll
    for (int j = 0; j < 16; j++)
        acc4[j] = cw[OFF_B4 + j];
#pragma unroll
    for (int j3 = 0; j3 < 32; j3 += 2) {
        u64 a0 = cw[OFF_B3 + j3];
        u64 a1 = cw[OFF_B3 + j3 + 1];
#pragma unroll
        for (int k = 0; k < 16; k += 2) {
            ulonglong2 w0 = cw2(OFF_W3 + j3 * 16 + k);
            ulonglong2 w1 = cw2(OFF_W3 + (j3 + 1) * 16 + k);
            a0 = fma2(h2[k],     w0.x, a0);
            a1 = fma2(h2[k],     w1.x, a1);
            a0 = fma2(h2[k + 1], w0.y, a0);
            a1 = fma2(h2[k + 1], w1.y, a1);
        }
        a0 = relu2(a0);
        a1 = relu2(a1);
#pragma unroll
        for (int j4 = 0; j4 < 16; j4 += 2) {
            ulonglong2 w0 = cw2(OFF_W4 + j3 * 16 + j4);        // k-major row j3
            ulonglong2 w1 = cw2(OFF_W4 + (j3 + 1) * 16 + j4);  // row j3+1
            acc4[j4]     = fma2(a0, w0.x, acc4[j4]);
            acc4[j4 + 1] = fma2(a0, w0.y, acc4[j4 + 1]);
            acc4[j4]     = fma2(a1, w1.x, acc4[j4]);
            acc4[j4 + 1] = fma2(a1, w1.y, acc4[j4 + 1]);
        }
    }
#pragma unroll
    for (int j = 0; j < 16; j++)
        acc4[j] = relu2(acc4[j]);
}

__global__ __launch_bounds__(128, 5)
void mlp_const_kernel(
    const float4* __restrict__ x,      // [N] rows of 4 floats
    float4* __restrict__ out)
{
    const long long tid = (long long)blockIdx.x * blockDim.x + threadIdx.x;
    const long long row = tid * 2;
    if (row >= NROWS) return;            // N even -> row+1 also valid

    float4 x0 = x[row];
    float4 x1 = x[row + 1];

    u64 h0[4];
    h0[0] = pack2(x0.x, x1.x);
    h0[1] = pack2(x0.y, x1.y);
    h0[2] = pack2(x0.z, x1.z);
    h0[3] = pack2(x0.w, x1.w);

    u64 h1[8];
    layer1x<4, 8, OFF_W1, OFF_B1>(h0, h1);

    u64 h2[16];
    layer1x<8, 16, OFF_W2, OFF_B2>(h1, h2);

    u64 acc4[16];
    fused34(h2, acc4);

    u64 h5[8];
    layer1x<16, 8, OFF_W5, OFF_B5>(acc4, h5);

    u64 h6[4];
    layer1x<8, 4, OFF_W6, OFF_B6>(h5, h6);

    float4 o0, o1;
    unpack2(h6[0], o0.x, o1.x);
    unpack2(h6[1], o0.y, o1.y);
    unpack2(h6[2], o0.z, o1.z);
    unpack2(h6[3], o0.w, o1.w);
    out[row]     = o0;
    out[row + 1] = o1;
}

extern "C" void kernel_launch(void* const* d_in, const int* in_sizes, int n_in,
                              void* d_out, int out_size)
{
    const float* x  = (const float*)d_in[0];
    const float* W1 = (const float*)d_in[1];
    const float* b1 = (const float*)d_in[2];
    const float* W2 = (const float*)d_in[3];
    const float* b2 = (const float*)d_in[4];
    const float* W3 = (const float*)d_in[5];
    const float* b3 = (const float*)d_in[6];
    const float* W4 = (const float*)d_in[7];
    const float* b4 = (const float*)d_in[8];
    const float* W5 = (const float*)d_in[9];
    const float* b5 = (const float*)d_in[10];
    const float* W6 = (const float*)d_in[11];
    const float* b6 = (const float*)d_in[12];

    // 1) repack weights into g_wbuf (dup'd pairs, transposed)
    repack_kernel<<<1, 256>>>(W1, b1, W2, b2, W3, b3, W4, b4, W5, b5, W6, b6);

    // 2) copy staging buffer into constant memory (D2D memcpy node)
    void* wbuf_addr = nullptr;
    cudaGetSymbolAddress(&wbuf_addr, g_wbuf);
    cudaMemcpyToSymbolAsync(cw, wbuf_addr, TOTAL_PAIRS * sizeof(u64), 0,
                            cudaMemcpyDeviceToDevice, 0);

    // 3) main kernel
    const int threads = 128;
    const long long nthreads = (NROWS + 1) / 2;
    const int blocks = (int)((nthreads + threads - 1) / threads);

    mlp_const_kernel<<<blocks, threads>>>((const float4*)x, (float4*)d_out);
}

// round 13
// speedup vs baseline: 1.2571x; 1.0509x over previous
#include <cuda_runtime.h>

// MLP: 4 -> 8 -> 16 -> 32 -> 16 -> 8 -> 4, ReLU after every layer. N=4M, fp32.
// Round 13: round-10 code (best: 4 rows/thread, const/UR weights, j-unroll x2)
// with block=64 + launch_bounds(64,7): 7x64 = 448 threads = 14 warps/SM, the
// exact register-file cap at 146 regs (128-thread blocks quantized to 12).

#define NROWS 4000000

typedef unsigned long long u64;

// ---- layout of the repacked weight buffer (units: 8-byte dup'd pairs) ----
static constexpr int OFF_W1 = 0,    OFF_B1 = 32;     // 4x8   (transposed [j][k])
static constexpr int OFF_W2 = 40,   OFF_B2 = 168;    // 8x16  (transposed)
static constexpr int OFF_W3 = 184,  OFF_B3 = 696;    // 16x32 (transposed)
static constexpr int OFF_W4 = 728,  OFF_B4 = 1240;   // 32x16 (k-major [k][j])
static constexpr int OFF_W5 = 1256, OFF_B5 = 1384;   // 16x8  (transposed)
static constexpr int OFF_W6 = 1392, OFF_B6 = 1424;   // 8x4   (transposed)
static constexpr int TOTAL_PAIRS = 1428;              // 11,424 bytes

__device__ u64 g_wbuf[TOTAL_PAIRS];        // staging (written by repack kernel)
__constant__ __align__(16) u64 cw[TOTAL_PAIRS];   // hot copy (memcpy node)

// ---- packed f32x2 helpers ------------------------------------------------

__device__ __forceinline__ u64 fma2(u64 a, u64 b, u64 c) {
    u64 d;
    asm("fma.rn.f32x2 %0, %1, %2, %3;" : "=l"(d) : "l"(a), "l"(b), "l"(c));
    return d;
}

__device__ __forceinline__ u64 pack2(float lo, float hi) {
    u64 d;
    asm("mov.b64 %0, {%1, %2};" : "=l"(d) : "f"(lo), "f"(hi));
    return d;
}

__device__ __forceinline__ void unpack2(u64 v, float& lo, float& hi) {
    asm("mov.b64 {%0, %1}, %2;" : "=f"(lo), "=f"(hi) : "l"(v));
}

// ReLU on a packed pair: two FMNMX on the register halves (alu pipe).
__device__ __forceinline__ u64 relu2(u64 v) {
    float lo, hi;
    unpack2(v, lo, hi);
    lo = fmaxf(lo, 0.0f);
    hi = fmaxf(hi, 0.0f);
    return pack2(lo, hi);
}

__device__ __forceinline__ u64 dup2(float w) { return pack2(w, w); }

// 128-bit constant load (two adjacent dup'd weight pairs).
__device__ __forceinline__ ulonglong2 cw2(int idx) {
    return *reinterpret_cast<const ulonglong2*>(&cw[idx]);
}

// ---- repack kernel: duplicate + transpose weights into g_wbuf -------------

__device__ __forceinline__ void fill_t(
    const float* __restrict__ W, const float* __restrict__ B,
    int offW, int offB, int K, int OUT)
{
    for (int t = threadIdx.x; t < K * OUT; t += blockDim.x) {
        int j = t / K;
        int k = t - j * K;
        g_wbuf[offW + t] = dup2(W[k * OUT + j]);   // transposed [j][k]
    }
    for (int t = threadIdx.x; t < OUT; t += blockDim.x)
        g_wbuf[offB + t] = dup2(B[t]);
}

__device__ __forceinline__ void fill_k(
    const float* __restrict__ W, const float* __restrict__ B,
    int offW, int offB, int K, int OUT)
{
    for (int t = threadIdx.x; t < K * OUT; t += blockDim.x)
        g_wbuf[offW + t] = dup2(W[t]);             // k-major [k][j] as stored
    for (int t = threadIdx.x; t < OUT; t += blockDim.x)
        g_wbuf[offB + t] = dup2(B[t]);
}

__global__ void repack_kernel(
    const float* __restrict__ W1, const float* __restrict__ b1,
    const float* __restrict__ W2, const float* __restrict__ b2,
    const float* __restrict__ W3, const float* __restrict__ b3,
    const float* __restrict__ W4, const float* __restrict__ b4,
    const float* __restrict__ W5, const float* __restrict__ b5,
    const float* __restrict__ W6, const float* __restrict__ b6)
{
    fill_t(W1, b1, OFF_W1, OFF_B1, 4, 8);
    fill_t(W2, b2, OFF_W2, OFF_B2, 8, 16);
    fill_t(W3, b3, OFF_W3, OFF_B3, 16, 32);
    fill_k(W4, b4, OFF_W4, OFF_B4, 32, 16);
    fill_t(W5, b5, OFF_W5, OFF_B5, 16, 8);
    fill_t(W6, b6, OFF_W6, OFF_B6, 8, 4);
}

// ---- main MLP kernel -------------------------------------------------------

// Layer on TWO row-pairs, output-j unrolled x2 -> 4 independent FMA chains.
template <int K, int OUT, int OFFW, int OFFB>
__device__ __forceinline__ void layer2x(
    const u64* hinA, const u64* hinB, u64* houtA, u64* houtB)
{
#pragma unroll
    for (int j = 0; j < OUT; j += 2) {
        u64 accA0 = cw[OFFB + j];
        u64 accB0 = accA0;
        u64 accA1 = cw[OFFB + j + 1];
        u64 accB1 = accA1;
#pragma unroll
        for (int k = 0; k < K; k += 2) {
            ulonglong2 w0 = cw2(OFFW + j * K + k);
            ulonglong2 w1 = cw2(OFFW + (j + 1) * K + k);
            accA0 = fma2(hinA[k],     w0.x, accA0);
            accB0 = fma2(hinB[k],     w0.x, accB0);
            accA1 = fma2(hinA[k],     w1.x, accA1);
            accB1 = fma2(hinB[k],     w1.x, accB1);
            accA0 = fma2(hinA[k + 1], w0.y, accA0);
            accB0 = fma2(hinB[k + 1], w0.y, accB0);
            accA1 = fma2(hinA[k + 1], w1.y, accA1);
            accB1 = fma2(hinB[k + 1], w1.y, accB1);
        }
        houtA[j]     = relu2(accA0);
        houtB[j]     = relu2(accB0);
        houtA[j + 1] = relu2(accA1);
        houtB[j + 1] = relu2(accB1);
    }
}

__global__ __launch_bounds__(64, 7)
void mlp_const_kernel(
    const float4* __restrict__ x,      // [N] rows of 4 floats
    float4* __restrict__ out)
{
    const long long tid = (long long)blockIdx.x * blockDim.x + threadIdx.x;
    const long long row = tid * 4;
    if (row >= NROWS) return;            // N % 4 == 0 -> all 4 rows valid

    // Pair A = rows (row, row+1), pair B = rows (row+2, row+3)
    float4 x0 = x[row];
    float4 x1 = x[row + 1];
    float4 x2 = x[row + 2];
    float4 x3 = x[row + 3];

    u64 h0A[4], h0B[4];
    h0A[0] = pack2(x0.x, x1.x);  h0B[0] = pack2(x2.x, x3.x);
    h0A[1] = pack2(x0.y, x1.y);  h0B[1] = pack2(x2.y, x3.y);
    h0A[2] = pack2(x0.z, x1.z);  h0B[2] = pack2(x2.z, x3.z);
    h0A[3] = pack2(x0.w, x1.w);  h0B[3] = pack2(x2.w, x3.w);

    u64 h1A[8], h1B[8];
    layer2x<4, 8, OFF_W1, OFF_B1>(h0A, h0B, h1A, h1B);

    u64 h2A[16], h2B[16];
    layer2x<8, 16, OFF_W2, OFF_B2>(h1A, h1B, h2A, h2B);

    // ---- fused layer3 (16->32) + layer4 (32->16), h3 streamed, j3 x2 ------
    u64 acc4A[16], acc4B[16];
    {
#pragma unroll
        for (int j = 0; j < 16; j++) {
            acc4A[j] = cw[OFF_B4 + j];
            acc4B[j] = acc4A[j];
        }
#pragma unroll
        for (int j3 = 0; j3 < 32; j3 += 2) {
            u64 aA0 = cw[OFF_B3 + j3];
            u64 aB0 = aA0;
            u64 aA1 = cw[OFF_B3 + j3 + 1];
            u64 aB1 = aA1;
#pragma unroll
            for (int k = 0; k < 16; k += 2) {
                ulonglong2 w0 = cw2(OFF_W3 + j3 * 16 + k);
                ulonglong2 w1 = cw2(OFF_W3 + (j3 + 1) * 16 + k);
                aA0 = fma2(h2A[k],     w0.x, aA0);
                aB0 = fma2(h2B[k],     w0.x, aB0);
                aA1 = fma2(h2A[k],     w1.x, aA1);
                aB1 = fma2(h2B[k],     w1.x, aB1);
                aA0 = fma2(h2A[k + 1], w0.y, aA0);
                aB0 = fma2(h2B[k + 1], w0.y, aB0);
                aA1 = fma2(h2A[k + 1], w1.y, aA1);
                aB1 = fma2(h2B[k + 1], w1.y, aB1);
            }
            aA0 = relu2(aA0);
            aB0 = relu2(aB0);
            aA1 = relu2(aA1);
            aB1 = relu2(aB1);
            // accumulate both h3 elements into all 16 layer-4 outputs
#pragma unroll
            for (int j4 = 0; j4 < 16; j4 += 2) {
                ulonglong2 w0 = cw2(OFF_W4 + j3 * 16 + j4);       // k-major row j3
                ulonglong2 w1 = cw2(OFF_W4 + (j3 + 1) * 16 + j4); // row j3+1
                acc4A[j4]     = fma2(aA0, w0.x, acc4A[j4]);
                acc4B[j4]     = fma2(aB0, w0.x, acc4B[j4]);
                acc4A[j4 + 1] = fma2(aA0, w0.y, acc4A[j4 + 1]);
                acc4B[j4 + 1] = fma2(aB0, w0.y, acc4B[j4 + 1]);
                acc4A[j4]     = fma2(aA1, w1.x, acc4A[j4]);
                acc4B[j4]     = fma2(aB1, w1.x, acc4B[j4]);
                acc4A[j4 + 1] = fma2(aA1, w1.y, acc4A[j4 + 1]);
                acc4B[j4 + 1] = fma2(aB1, w1.y, acc4B[j4 + 1]);
            }
        }
#pragma unroll
        for (int j = 0; j < 16; j++) {
            acc4A[j] = relu2(acc4A[j]);
            acc4B[j] = relu2(acc4B[j]);
        }
    }

    u64 h5A[8], h5B[8];
    layer2x<16, 8, OFF_W5, OFF_B5>(acc4A, acc4B, h5A, h5B);

    u64 h6A[4], h6B[4];
    layer2x<8, 4, OFF_W6, OFF_B6>(h5A, h5B, h6A, h6B);

    float4 o0, o1, o2, o3;
    unpack2(h6A[0], o0.x, o1.x);  unpack2(h6B[0], o2.x, o3.x);
    unpack2(h6A[1], o0.y, o1.y);  unpack2(h6B[1], o2.y, o3.y);
    unpack2(h6A[2], o0.z, o1.z);  unpack2(h6B[2], o2.z, o3.z);
    unpack2(h6A[3], o0.w, o1.w);  unpack2(h6B[3], o2.w, o3.w);
    out[row]     = o0;
    out[row + 1] = o1;
    out[row + 2] = o2;
    out[row + 3] = o3;
}

extern "C" void kernel_launch(void* const* d_in, const int* in_sizes, int n_in,
                              void* d_out, int out_size)
{
    const float* x  = (const float*)d_in[0];
    const float* W1 = (const float*)d_in[1];
    const float* b1 = (const float*)d_in[2];
    const float* W2 = (const float*)d_in[3];
    const float* b2 = (const float*)d_in[4];
    const float* W3 = (const float*)d_in[5];
    const float* b3 = (const float*)d_in[6];
    const float* W4 = (const float*)d_in[7];
    const float* b4 = (const float*)d_in[8];
    const float* W5 = (const float*)d_in[9];
    const float* b5 = (const float*)d_in[10];
    const float* W6 = (const float*)d_in[11];
    const float* b6 = (const float*)d_in[12];

    // 1) repack weights into g_wbuf (dup'd pairs, transposed)
    repack_kernel<<<1, 256>>>(W1, b1, W2, b2, W3, b3, W4, b4, W5, b5, W6, b6);

    // 2) copy staging buffer into constant memory (D2D memcpy node)
    void* wbuf_addr = nullptr;
    cudaGetSymbolAddress(&wbuf_addr, g_wbuf);
    cudaMemcpyToSymbolAsync(cw, wbuf_addr, TOTAL_PAIRS * sizeof(u64), 0,
                            cudaMemcpyDeviceToDevice, 0);

    // 3) main kernel
    const int threads = 64;
    const long long nthreads = (NROWS + 3) / 4;
    const int blocks = (int)((nthreads + threads - 1) / threads);

    mlp_const_kernel<<<blocks, threads>>>((const float4*)x, (float4*)d_out);
}

// round 15
// speedup vs baseline: 1.5297x; 1.2169x over previous
#include <cuda_runtime.h>

// MLP: 4 -> 8 -> 16 -> 32 -> 16 -> 8 -> 4, ReLU after every layer. N=4M, fp32.
// Round 15: round-10 code (4 rows/thread, const/UR weights, j-unroll x2) with
// __maxnreg__(144) ONLY (launch_bounds+maxnreg are mutually exclusive) and
// block=64: 65536/(144*64) -> 7 blocks/SM = 448 threads = 14 warps (3.5/SMSP),
// vs 12 warps at round 10. 144 needs just a 2-reg shave from the natural 146.

#define NROWS 4000000

typedef unsigned long long u64;

// ---- layout of the repacked weight buffer (units: 8-byte dup'd pairs) ----
static constexpr int OFF_W1 = 0,    OFF_B1 = 32;     // 4x8   (transposed [j][k])
static constexpr int OFF_W2 = 40,   OFF_B2 = 168;    // 8x16  (transposed)
static constexpr int OFF_W3 = 184,  OFF_B3 = 696;    // 16x32 (transposed)
static constexpr int OFF_W4 = 728,  OFF_B4 = 1240;   // 32x16 (k-major [k][j])
static constexpr int OFF_W5 = 1256, OFF_B5 = 1384;   // 16x8  (transposed)
static constexpr int OFF_W6 = 1392, OFF_B6 = 1424;   // 8x4   (transposed)
static constexpr int TOTAL_PAIRS = 1428;              // 11,424 bytes

__device__ u64 g_wbuf[TOTAL_PAIRS];        // staging (written by repack kernel)
__constant__ __align__(16) u64 cw[TOTAL_PAIRS];   // hot copy (memcpy node)

// ---- packed f32x2 helpers ------------------------------------------------

__device__ __forceinline__ u64 fma2(u64 a, u64 b, u64 c) {
    u64 d;
    asm("fma.rn.f32x2 %0, %1, %2, %3;" : "=l"(d) : "l"(a), "l"(b), "l"(c));
    return d;
}

__device__ __forceinline__ u64 pack2(float lo, float hi) {
    u64 d;
    asm("mov.b64 %0, {%1, %2};" : "=l"(d) : "f"(lo), "f"(hi));
    return d;
}

__device__ __forceinline__ void unpack2(u64 v, float& lo, float& hi) {
    asm("mov.b64 {%0, %1}, %2;" : "=f"(lo), "=f"(hi) : "l"(v));
}

// ReLU on a packed pair: two FMNMX on the register halves (alu pipe).
__device__ __forceinline__ u64 relu2(u64 v) {
    float lo, hi;
    unpack2(v, lo, hi);
    lo = fmaxf(lo, 0.0f);
    hi = fmaxf(hi, 0.0f);
    return pack2(lo, hi);
}

__device__ __forceinline__ u64 dup2(float w) { return pack2(w, w); }

// 128-bit constant load (two adjacent dup'd weight pairs).
__device__ __forceinline__ ulonglong2 cw2(int idx) {
    return *reinterpret_cast<const ulonglong2*>(&cw[idx]);
}

// ---- repack kernel: duplicate + transpose weights into g_wbuf -------------

__device__ __forceinline__ void fill_t(
    const float* __restrict__ W, const float* __restrict__ B,
    int offW, int offB, int K, int OUT)
{
    for (int t = threadIdx.x; t < K * OUT; t += blockDim.x) {
        int j = t / K;
        int k = t - j * K;
        g_wbuf[offW + t] = dup2(W[k * OUT + j]);   // transposed [j][k]
    }
    for (int t = threadIdx.x; t < OUT; t += blockDim.x)
        g_wbuf[offB + t] = dup2(B[t]);
}

__device__ __forceinline__ void fill_k(
    const float* __restrict__ W, const float* __restrict__ B,
    int offW, int offB, int K, int OUT)
{
    for (int t = threadIdx.x; t < K * OUT; t += blockDim.x)
        g_wbuf[offW + t] = dup2(W[t]);             // k-major [k][j] as stored
    for (int t = threadIdx.x; t < OUT; t += blockDim.x)
        g_wbuf[offB + t] = dup2(B[t]);
}

__global__ void repack_kernel(
    const float* __restrict__ W1, const float* __restrict__ b1,
    const float* __restrict__ W2, const float* __restrict__ b2,
    const float* __restrict__ W3, const float* __restrict__ b3,
    const float* __restrict__ W4, const float* __restrict__ b4,
    const float* __restrict__ W5, const float* __restrict__ b5,
    const float* __restrict__ W6, const float* __restrict__ b6)
{
    fill_t(W1, b1, OFF_W1, OFF_B1, 4, 8);
    fill_t(W2, b2, OFF_W2, OFF_B2, 8, 16);
    fill_t(W3, b3, OFF_W3, OFF_B3, 16, 32);
    fill_k(W4, b4, OFF_W4, OFF_B4, 32, 16);
    fill_t(W5, b5, OFF_W5, OFF_B5, 16, 8);
    fill_t(W6, b6, OFF_W6, OFF_B6, 8, 4);
}

// ---- main MLP kernel -------------------------------------------------------

// Layer on TWO row-pairs, output-j unrolled x2 -> 4 independent FMA chains.
template <int K, int OUT, int OFFW, int OFFB>
__device__ __forceinline__ void layer2x(
    const u64* hinA, const u64* hinB, u64* houtA, u64* houtB)
{
#pragma unroll
    for (int j = 0; j < OUT; j += 2) {
        u64 accA0 = cw[OFFB + j];
        u64 accB0 = accA0;
        u64 accA1 = cw[OFFB + j + 1];
        u64 accB1 = accA1;
#pragma unroll
        for (int k = 0; k < K; k += 2) {
            ulonglong2 w0 = cw2(OFFW + j * K + k);
            ulonglong2 w1 = cw2(OFFW + (j + 1) * K + k);
            accA0 = fma2(hinA[k],     w0.x, accA0);
            accB0 = fma2(hinB[k],     w0.x, accB0);
            accA1 = fma2(hinA[k],     w1.x, accA1);
            accB1 = fma2(hinB[k],     w1.x, accB1);
            accA0 = fma2(hinA[k + 1], w0.y, accA0);
            accB0 = fma2(hinB[k + 1], w0.y, accB0);
            accA1 = fma2(hinA[k + 1], w1.y, accA1);
            accB1 = fma2(hinB[k + 1], w1.y, accB1);
        }
        houtA[j]     = relu2(accA0);
        houtB[j]     = relu2(accB0);
        houtA[j + 1] = relu2(accA1);
        houtB[j + 1] = relu2(accB1);
    }
}

__global__ __maxnreg__(144)
void mlp_const_kernel(
    const float4* __restrict__ x,      // [N] rows of 4 floats
    float4* __restrict__ out)
{
    const unsigned tid = blockIdx.x * 64u + threadIdx.x;
    const unsigned row = tid * 4u;
    if (row >= NROWS) return;            // N % 4 == 0 -> all 4 rows valid

    // Pair A = rows (row, row+1), pair B = rows (row+2, row+3)
    float4 x0 = x[row];
    float4 x1 = x[row + 1];
    float4 x2 = x[row + 2];
    float4 x3 = x[row + 3];

    u64 h0A[4], h0B[4];
    h0A[0] = pack2(x0.x, x1.x);  h0B[0] = pack2(x2.x, x3.x);
    h0A[1] = pack2(x0.y, x1.y);  h0B[1] = pack2(x2.y, x3.y);
    h0A[2] = pack2(x0.z, x1.z);  h0B[2] = pack2(x2.z, x3.z);
    h0A[3] = pack2(x0.w, x1.w);  h0B[3] = pack2(x2.w, x3.w);

    u64 h1A[8], h1B[8];
    layer2x<4, 8, OFF_W1, OFF_B1>(h0A, h0B, h1A, h1B);

    u64 h2A[16], h2B[16];
    layer2x<8, 16, OFF_W2, OFF_B2>(h1A, h1B, h2A, h2B);

    // ---- fused layer3 (16->32) + layer4 (32->16), h3 streamed, j3 x2 ------
    u64 acc4A[16], acc4B[16];
    {
#pragma unroll
        for (int j = 0; j < 16; j++) {
            acc4A[j] = cw[OFF_B4 + j];
            acc4B[j] = acc4A[j];
        }
#pragma unroll
        for (int j3 = 0; j3 < 32; j3 += 2) {
            u64 aA0 = cw[OFF_B3 + j3];
            u64 aB0 = aA0;
            u64 aA1 = cw[OFF_B3 + j3 + 1];
            u64 aB1 = aA1;
#pragma unroll
            for (int k = 0; k < 16; k += 2) {
                ulonglong2 w0 = cw2(OFF_W3 + j3 * 16 + k);
                ulonglong2 w1 = cw2(OFF_W3 + (j3 + 1) * 16 + k);
                aA0 = fma2(h2A[k],     w0.x, aA0);
                aB0 = fma2(h2B[k],     w0.x, aB0);
                aA1 = fma2(h2A[k],     w1.x, aA1);
                aB1 = fma2(h2B[k],     w1.x, aB1);
                aA0 = fma2(h2A[k + 1], w0.y, aA0);
                aB0 = fma2(h2B[k + 1], w0.y, aB0);
                aA1 = fma2(h2A[k + 1], w1.y, aA1);
                aB1 = fma2(h2B[k + 1], w1.y, aB1);
            }
            aA0 = relu2(aA0);
            aB0 = relu2(aB0);
            aA1 = relu2(aA1);
            aB1 = relu2(aB1);
            // accumulate both h3 elements into all 16 layer-4 outputs
#pragma unroll
            for (int j4 = 0; j4 < 16; j4 += 2) {
                ulonglong2 w0 = cw2(OFF_W4 + j3 * 16 + j4);       // k-major row j3
                ulonglong2 w1 = cw2(OFF_W4 + (j3 + 1) * 16 + j4); // row j3+1
                acc4A[j4]     = fma2(aA0, w0.x, acc4A[j4]);
                acc4B[j4]     = fma2(aB0, w0.x, acc4B[j4]);
                acc4A[j4 + 1] = fma2(aA0, w0.y, acc4A[j4 + 1]);
                acc4B[j4 + 1] = fma2(aB0, w0.y, acc4B[j4 + 1]);
                acc4A[j4]     = fma2(aA1, w1.x, acc4A[j4]);
                acc4B[j4]     = fma2(aB1, w1.x, acc4B[j4]);
                acc4A[j4 + 1] = fma2(aA1, w1.y, acc4A[j4 + 1]);
                acc4B[j4 + 1] = fma2(aB1, w1.y, acc4B[j4 + 1]);
            }
        }
#pragma unroll
        for (int j = 0; j < 16; j++) {
            acc4A[j] = relu2(acc4A[j]);
            acc4B[j] = relu2(acc4B[j]);
        }
    }

    u64 h5A[8], h5B[8];
    layer2x<16, 8, OFF_W5, OFF_B5>(acc4A, acc4B, h5A, h5B);

    u64 h6A[4], h6B[4];
    layer2x<8, 4, OFF_W6, OFF_B6>(h5A, h5B, h6A, h6B);

    float4 o0, o1, o2, o3;
    unpack2(h6A[0], o0.x, o1.x);  unpack2(h6B[0], o2.x, o3.x);
    unpack2(h6A[1], o0.y, o1.y);  unpack2(h6B[1], o2.y, o3.y);
    unpack2(h6A[2], o0.z, o1.z);  unpack2(h6B[2], o2.z, o3.z);
    unpack2(h6A[3], o0.w, o1.w);  unpack2(h6B[3], o2.w, o3.w);
    out[row]     = o0;
    out[row + 1] = o1;
    out[row + 2] = o2;
    out[row + 3] = o3;
}

extern "C" void kernel_launch(void* const* d_in, const int* in_sizes, int n_in,
                              void* d_out, int out_size)
{
    const float* x  = (const float*)d_in[0];
    const float* W1 = (const float*)d_in[1];
    const float* b1 = (const float*)d_in[2];
    const float* W2 = (const float*)d_in[3];
    const float* b2 = (const float*)d_in[4];
    const float* W3 = (const float*)d_in[5];
    const float* b3 = (const float*)d_in[6];
    const float* W4 = (const float*)d_in[7];
    const float* b4 = (const float*)d_in[8];
    const float* W5 = (const float*)d_in[9];
    const float* b5 = (const float*)d_in[10];
    const float* W6 = (const float*)d_in[11];
    const float* b6 = (const float*)d_in[12];

    // 1) repack weights into g_wbuf (dup'd pairs, transposed)
    repack_kernel<<<1, 256>>>(W1, b1, W2, b2, W3, b3, W4, b4, W5, b5, W6, b6);

    // 2) copy staging buffer into constant memory (D2D memcpy node)
    void* wbuf_addr = nullptr;
    cudaGetSymbolAddress(&wbuf_addr, g_wbuf);
    cudaMemcpyToSymbolAsync(cw, wbuf_addr, TOTAL_PAIRS * sizeof(u64), 0,
                            cudaMemcpyDeviceToDevice, 0);

    // 3) main kernel
    const int threads = 64;
    const int nthreads = (NROWS + 3) / 4;
    const int blocks = (nthreads + threads - 1) / threads;

    mlp_const_kernel<<<blocks, threads>>>((const float4*)x, (float4*)d_out);
}